// round 2
// baseline (speedup 1.0000x reference)
#include <cuda_runtime.h>
#include <cstdint>

// Problem constants
#define R_TOTAL 131072      // N*B*H rows
#define BHD     8388608     // B*DIM = 8192*1024 (one output tensor)
#define TM 128
#define TN 64
#define KC 16
#define NTH 256

#define A1 (TM * (KC + 1))   // 2176 words per A buffer
#define B1 (TN * (KC + 1))   // 1088 words per B buffer
#define SMEM_WORDS (4 * A1 + 4 * B1)   // [2 buf][2 part] for A and B
#define SMEM_BYTES (SMEM_WORDS * 4)    // 52224

// Scratch (device globals — no allocation allowed in kernel_launch)
__device__ float g_h1[131072 * 512];   // relu(layer1) for both branches
__device__ float g_st[131072 * 512];   // cols 0-255: axis logits s; 256-511: arg t
__device__ float g_w1c[512 * 512];     // folded layer-1 weights
__device__ float g_b1c[512];

// ---------------------------------------------------------------------------
// Prep: fold concat([axis-arg/2, axis+arg/2]) @ W1^T into direct weights on
// [axis, arg]:  coeff(axis) = Wlo + Whi ; coeff(arg) = (Whi - Wlo)/2
// ---------------------------------------------------------------------------
__global__ void prep_kernel(const float* __restrict__ Wax1, const float* __restrict__ bax1,
                            const float* __restrict__ Warg1, const float* __restrict__ barg1)
{
    int idx = blockIdx.x * blockDim.x + threadIdx.x;   // 0 .. 262143
    int o = idx >> 9;
    int i = idx & 511;
    const float* Ws = (o < 256) ? Wax1 : Warg1;
    int ro = (o < 256) ? o : (o - 256);
    float w;
    if (i < 256) {
        w = Ws[ro * 512 + i] + Ws[ro * 512 + 256 + i];
    } else {
        int ii = i - 256;
        w = 0.5f * (Ws[ro * 512 + 256 + ii] - Ws[ro * 512 + ii]);
    }
    g_w1c[o * 512 + i] = w;
    if (i == 0)
        g_b1c[o] = (o < 256) ? bax1[o] : barg1[o - 256];
}

// ---------------------------------------------------------------------------
// 3xTF32 GEMM:  C[m][n] = sum_k X[m][k] * W[n][k]  (+bias, optional relu)
// Each operand split v = hi + lo (tf32 each); acc += hi*lo + lo*hi + hi*hi.
// CTA tile 128x64, 8 warps (2x4), warp tile 64x16, mma.m16n8k8.tf32.
// ---------------------------------------------------------------------------
__device__ __forceinline__ unsigned f2tf(float f)
{
    unsigned u;
    asm("cvt.rna.tf32.f32 %0, %1;" : "=r"(u) : "f"(f));
    return u;
}

__device__ __forceinline__ void split_tf(float v, unsigned& h, unsigned& l)
{
    h = f2tf(v);
    l = f2tf(v - __uint_as_float(h));
}

#define MMA(d, a0, a1, a2, a3, b0, b1)                                        \
    asm volatile(                                                             \
        "mma.sync.aligned.m16n8k8.row.col.f32.tf32.tf32.f32 "                 \
        "{%0,%1,%2,%3}, {%4,%5,%6,%7}, {%8,%9}, {%0,%1,%2,%3};"               \
        : "+f"(d[0]), "+f"(d[1]), "+f"(d[2]), "+f"(d[3])                      \
        : "r"(a0), "r"(a1), "r"(a2), "r"(a3), "r"(b0), "r"(b1))

__global__ __launch_bounds__(NTH)
void gemm_tf32(const float* __restrict__ src0, int lda0,
               const float* __restrict__ src1, int lda1, int K0, int K,
               const float* __restrict__ W, int ldw,
               const float* __restrict__ bias,
               float* __restrict__ C, int ldc, int relu)
{
    extern __shared__ unsigned sm[];
    unsigned* Ab = sm;               // [buf][part][TM][KC+1]
    unsigned* Bb = sm + 4 * A1;      // [buf][part][TN][KC+1]

    const int tid  = threadIdx.x;
    const int lane = tid & 31;
    const int wid  = tid >> 5;
    const int gp   = lane >> 2;      // 0..7
    const int tq   = lane & 3;       // 0..3
    const int wm   = wid >> 2;       // 0..1
    const int wn   = wid & 3;        // 0..3
    const int mbase = blockIdx.x * TM;
    const int nbase = blockIdx.y * TN;

    float acc[4][2][4];
    #pragma unroll
    for (int a = 0; a < 4; a++)
        #pragma unroll
        for (int b = 0; b < 2; b++)
            #pragma unroll
            for (int c = 0; c < 4; c++) acc[a][b][c] = 0.f;

    const int NCH = K / KC;
    float4 ra[2], rb;
    const int brow = tid >> 2;     // B staging row (0..63)
    const int bc4  = tid & 3;      // B staging float4 idx within row

    for (int ch = 0; ch < NCH + 1; ++ch) {
        // ---- stage next chunk global -> regs ----
        if (ch < NCH) {
            int kg = ch * KC;
            const float* S;
            int ld, kk;
            if (kg < K0) { S = src0; ld = lda0; kk = kg; }
            else         { S = src1; ld = lda1; kk = kg - K0; }
            #pragma unroll
            for (int i = 0; i < 2; i++) {
                int idx = tid + i * 256;
                int row = idx >> 2;
                int c4  = idx & 3;
                ra[i] = *(const float4*)(S + (size_t)(mbase + row) * ld + kk + c4 * 4);
            }
            rb = *(const float4*)(W + (size_t)(nbase + brow) * ldw + kg + bc4 * 4);
        }

        // ---- compute previous chunk from smem ----
        if (ch > 0) {
            int bf = (ch - 1) & 1;
            const unsigned* Ah = Ab + (bf * 2 + 0) * A1;
            const unsigned* Al = Ab + (bf * 2 + 1) * A1;
            const unsigned* Bh = Bb + (bf * 2 + 0) * B1;
            const unsigned* Bl = Bb + (bf * 2 + 1) * B1;
            #pragma unroll
            for (int ks = 0; ks < 2; ks++) {
                int kk = ks * 8;
                unsigned ah[4][4], al[4][4], bh[2][2], bl[2][2];
                #pragma unroll
                for (int mt = 0; mt < 4; mt++) {
                    int r0 = wm * 64 + mt * 16 + gp;
                    int i00 = r0 * (KC + 1) + kk + tq;
                    int i10 = (r0 + 8) * (KC + 1) + kk + tq;
                    ah[mt][0] = Ah[i00];     al[mt][0] = Al[i00];
                    ah[mt][1] = Ah[i10];     al[mt][1] = Al[i10];
                    ah[mt][2] = Ah[i00 + 4]; al[mt][2] = Al[i00 + 4];
                    ah[mt][3] = Ah[i10 + 4]; al[mt][3] = Al[i10 + 4];
                }
                #pragma unroll
                for (int nt = 0; nt < 2; nt++) {
                    int n0 = wn * 16 + nt * 8 + gp;
                    int i0 = n0 * (KC + 1) + kk + tq;
                    bh[nt][0] = Bh[i0];     bl[nt][0] = Bl[i0];
                    bh[nt][1] = Bh[i0 + 4]; bl[nt][1] = Bl[i0 + 4];
                }
                #pragma unroll
                for (int mt = 0; mt < 4; mt++)
                    #pragma unroll
                    for (int nt = 0; nt < 2; nt++) {
                        MMA(acc[mt][nt], ah[mt][0], ah[mt][1], ah[mt][2], ah[mt][3],
                            bl[nt][0], bl[nt][1]);
                        MMA(acc[mt][nt], al[mt][0], al[mt][1], al[mt][2], al[mt][3],
                            bh[nt][0], bh[nt][1]);
                        MMA(acc[mt][nt], ah[mt][0], ah[mt][1], ah[mt][2], ah[mt][3],
                            bh[nt][0], bh[nt][1]);
                    }
            }
        }

        // ---- store staged chunk to smem (hi/lo split) ----
        if (ch < NCH) {
            int bf = ch & 1;
            unsigned* Ah = Ab + (bf * 2 + 0) * A1;
            unsigned* Al = Ab + (bf * 2 + 1) * A1;
            unsigned* Bh = Bb + (bf * 2 + 0) * B1;
            unsigned* Bl = Bb + (bf * 2 + 1) * B1;
            #pragma unroll
            for (int i = 0; i < 2; i++) {
                int idx = tid + i * 256;
                int row = idx >> 2;
                int c4  = idx & 3;
                float v[4] = {ra[i].x, ra[i].y, ra[i].z, ra[i].w};
                #pragma unroll
                for (int j = 0; j < 4; j++) {
                    unsigned h, l;
                    split_tf(v[j], h, l);
                    Ah[row * (KC + 1) + c4 * 4 + j] = h;
                    Al[row * (KC + 1) + c4 * 4 + j] = l;
                }
            }
            {
                float v[4] = {rb.x, rb.y, rb.z, rb.w};
                #pragma unroll
                for (int j = 0; j < 4; j++) {
                    unsigned h, l;
                    split_tf(v[j], h, l);
                    Bh[brow * (KC + 1) + bc4 * 4 + j] = h;
                    Bl[brow * (KC + 1) + bc4 * 4 + j] = l;
                }
            }
            __syncthreads();
        }
    }

    // ---- epilogue: bias (+relu), store ----
    #pragma unroll
    for (int mt = 0; mt < 4; mt++) {
        int r0 = mbase + wm * 64 + mt * 16 + gp;
        #pragma unroll
        for (int nt = 0; nt < 2; nt++) {
            int c0 = nbase + wn * 16 + nt * 8 + tq * 2;
            float bv0 = bias[c0];
            float bv1 = bias[c0 + 1];
            float v;
            v = acc[mt][nt][0] + bv0; if (relu) v = fmaxf(v, 0.f);
            C[(size_t)r0 * ldc + c0] = v;
            v = acc[mt][nt][1] + bv1; if (relu) v = fmaxf(v, 0.f);
            C[(size_t)r0 * ldc + c0 + 1] = v;
            v = acc[mt][nt][2] + bv0; if (relu) v = fmaxf(v, 0.f);
            C[(size_t)(r0 + 8) * ldc + c0] = v;
            v = acc[mt][nt][3] + bv1; if (relu) v = fmaxf(v, 0.f);
            C[(size_t)(r0 + 8) * ldc + c0 + 1] = v;
        }
    }
}

// ---------------------------------------------------------------------------
// Epilogue: per (bh, d): softmax over N=4 of s, circular mean via atan
// correction; gate = sigmoid(mean_n t); arg_out = min_n(arg) * gate.
// ---------------------------------------------------------------------------
__global__ void epilogue_kernel(const float* __restrict__ axisE,
                                const float* __restrict__ argE,
                                float* __restrict__ out)
{
    int idx = blockIdx.x * blockDim.x + threadIdx.x;   // 0 .. BHD-1
    int bh = idx >> 8;
    int d  = idx & 255;

    float s[4], axv[4], agv[4], tsum = 0.f;
    #pragma unroll
    for (int n = 0; n < 4; n++) {
        size_t r = (size_t)n * 32768 + bh;
        s[n]   = g_st[r * 512 + d];
        tsum  += g_st[r * 512 + 256 + d];
        axv[n] = axisE[r * 256 + d];
        agv[n] = argE [r * 256 + d];
    }

    float m = fmaxf(fmaxf(s[0], s[1]), fmaxf(s[2], s[3]));
    float e[4], se = 0.f;
    #pragma unroll
    for (int n = 0; n < 4; n++) { e[n] = expf(s[n] - m); se += e[n]; }
    float inv = 1.f / se;

    float x = 0.f, y = 0.f;
    #pragma unroll
    for (int n = 0; n < 4; n++) {
        float sn, cn;
        sincosf(axv[n], &sn, &cn);
        float w = e[n] * inv;
        x += w * cn;
        y += w * sn;
    }
    if (fabsf(x) < 0.001f) x = 0.001f;   // jnp.where(|x|<1e-3, +1e-3, x)
    float ao = atanf(y / x);
    if (x < 0.f) ao += (y < 0.f) ? -3.14159265358979f : 3.14159265358979f;

    float gate = 1.f / (1.f + expf(-0.25f * tsum));
    float mn = fminf(fminf(agv[0], agv[1]), fminf(agv[2], agv[3]));

    out[idx]       = ao;
    out[BHD + idx] = mn * gate;
}

// ---------------------------------------------------------------------------
extern "C" void kernel_launch(void* const* d_in, const int* in_sizes, int n_in,
                              void* d_out, int out_size)
{
    const float* axisE = (const float*)d_in[0];
    const float* argE  = (const float*)d_in[1];
    const float* Wax1  = (const float*)d_in[2];
    const float* bax1  = (const float*)d_in[3];
    const float* Warg1 = (const float*)d_in[4];
    const float* barg1 = (const float*)d_in[5];
    const float* Wax2  = (const float*)d_in[6];
    const float* bax2  = (const float*)d_in[7];
    const float* Warg2 = (const float*)d_in[8];
    const float* barg2 = (const float*)d_in[9];

    float *h1, *st, *w1c, *b1c;
    cudaGetSymbolAddress((void**)&h1,  g_h1);
    cudaGetSymbolAddress((void**)&st,  g_st);
    cudaGetSymbolAddress((void**)&w1c, g_w1c);
    cudaGetSymbolAddress((void**)&b1c, g_b1c);

    cudaFuncSetAttribute(gemm_tf32, cudaFuncAttributeMaxDynamicSharedMemorySize,
                         SMEM_BYTES);

    // Fold layer-1 weights
    prep_kernel<<<1024, 256>>>(Wax1, bax1, Warg1, barg1);

    // GEMM1: h1 = relu([axis,arg] @ W1c^T + b1c), [131072 x 512]
    gemm_tf32<<<dim3(R_TOTAL / TM, 512 / TN), NTH, SMEM_BYTES>>>(
        axisE, 256, argE, 256, 256, 512, w1c, 512, b1c, h1, 512, 1);

    // GEMM2a: s = h1[:,0:256] @ W_axis2^T + b_axis2   -> st[:,0:256]
    gemm_tf32<<<dim3(R_TOTAL / TM, 256 / TN), NTH, SMEM_BYTES>>>(
        h1, 512, h1, 512, 256, 256, Wax2, 256, bax2, st, 512, 0);

    // GEMM2b: t = h1[:,256:512] @ W_arg2^T + b_arg2   -> st[:,256:511]
    gemm_tf32<<<dim3(R_TOTAL / TM, 256 / TN), NTH, SMEM_BYTES>>>(
        h1 + 256, 512, h1 + 256, 512, 256, 256, Warg2, 256, barg2, st + 256, 512, 0);

    // Fused softmax / circular mean / gate epilogue
    epilogue_kernel<<<BHD / 256, 256>>>(axisE, argE, (float*)d_out);
}

// round 5
// speedup vs baseline: 1.5508x; 1.5508x over previous
#include <cuda_runtime.h>
#include <cstdint>

// Problem constants
#define R_TOTAL 131072      // N*B*H rows
#define BH      32768       // B*H
#define BHD     8388608     // B*DIM
#define TM 128
#define TN 64
#define KC 16
#define KS 20               // padded smem row stride (words)
#define NTH 256

// Scratch (device globals — no allocation allowed in kernel_launch)
__device__ float g_h1[131072 * 512];   // relu(layer1): cols 0-255 axis, 256-511 arg
__device__ float g_s [131072 * 256];   // axis logits
__device__ float g_hb[32768 * 256];    // mean over N of arg-branch h1
__device__ float g_t [32768 * 256];    // gate pre-activation
__device__ float g_w1c[512 * 512];     // folded layer-1 weights
__device__ float g_b1c[512];

// ---------------------------------------------------------------------------
// Prep: fold concat([axis-arg/2, axis+arg/2]) @ W1^T into direct weights on
// [axis, arg]:  coeff(axis) = Wlo + Whi ; coeff(arg) = (Whi - Wlo)/2
// ---------------------------------------------------------------------------
__global__ void prep_kernel(const float* __restrict__ Wax1, const float* __restrict__ bax1,
                            const float* __restrict__ Warg1, const float* __restrict__ barg1)
{
    int idx = blockIdx.x * blockDim.x + threadIdx.x;   // 0 .. 262143
    int o = idx >> 9;
    int i = idx & 511;
    const float* Ws = (o < 256) ? Wax1 : Warg1;
    int ro = o & 255;
    float w;
    if (i < 256) {
        w = Ws[ro * 512 + i] + Ws[ro * 512 + 256 + i];
    } else {
        int ii = i - 256;
        w = 0.5f * (Ws[ro * 512 + 256 + ii] - Ws[ro * 512 + ii]);
    }
    g_w1c[o * 512 + i] = w;
    if (i == 0)
        g_b1c[o] = (o < 256) ? bax1[o] : barg1[o - 256];
}

// ---------------------------------------------------------------------------
// 3xTF32 GEMM, register-split variant:
// smem holds raw fp32; fragments split in regs: hi = cvt.rna.tf32(v),
// lo = v - hi (fed unrounded; mma truncates -> error ~2^-23, negligible).
// acc += hi*lo + lo*hi + hi*hi.
// CTA tile 128x64, 8 warps (2x4), warp tile 64x16, mma.m16n8k8.tf32.
// grid: (x = N blocks, y = M blocks) so same-row CTAs run together (L2 reuse).
// ---------------------------------------------------------------------------
__device__ __forceinline__ unsigned f2tf(float f)
{
    unsigned u;
    asm("cvt.rna.tf32.f32 %0, %1;" : "=r"(u) : "f"(f));
    return u;
}

__device__ __forceinline__ void split2(float v, unsigned& h, unsigned& l)
{
    h = f2tf(v);
    l = __float_as_uint(v - __uint_as_float(h));
}

#define MMA(d, a0, a1, a2, a3, b0, b1)                                        \
    asm volatile(                                                             \
        "mma.sync.aligned.m16n8k8.row.col.f32.tf32.tf32.f32 "                 \
        "{%0,%1,%2,%3}, {%4,%5,%6,%7}, {%8,%9}, {%0,%1,%2,%3};"               \
        : "+f"(d[0]), "+f"(d[1]), "+f"(d[2]), "+f"(d[3])                      \
        : "r"(a0), "r"(a1), "r"(a2), "r"(a3), "r"(b0), "r"(b1))

__global__ __launch_bounds__(NTH, 2)
void gemm_tf32(const float* __restrict__ src0, int lda0,
               const float* __restrict__ src1, int lda1, int K0, int K,
               const float* __restrict__ W, int ldw,
               const float* __restrict__ bias,
               float* __restrict__ C, int ldc, int relu)
{
    __shared__ float As[2][TM][KS];
    __shared__ float Bs[2][TN][KS];

    const int tid  = threadIdx.x;
    const int lane = tid & 31;
    const int wid  = tid >> 5;
    const int gp   = lane >> 2;      // 0..7
    const int tq   = lane & 3;       // 0..3
    const int wm   = wid >> 2;       // 0..1
    const int wn   = wid & 3;        // 0..3
    const int mbase = blockIdx.y * TM;
    const int nbase = blockIdx.x * TN;

    float acc[4][2][4];
    #pragma unroll
    for (int a = 0; a < 4; a++)
        #pragma unroll
        for (int b = 0; b < 2; b++)
            #pragma unroll
            for (int c = 0; c < 4; c++) acc[a][b][c] = 0.f;

    const int NCH = K / KC;
    float4 ra[2], rb;
    const int brow = tid >> 2;     // B staging row (0..63)
    const int bc4  = tid & 3;      // B staging float4 idx within row

    for (int ch = 0; ch < NCH + 1; ++ch) {
        // ---- stage next chunk global -> regs ----
        if (ch < NCH) {
            int kg = ch * KC;
            const float* S;
            int ld, kk;
            if (kg < K0) { S = src0; ld = lda0; kk = kg; }
            else         { S = src1; ld = lda1; kk = kg - K0; }
            #pragma unroll
            for (int i = 0; i < 2; i++) {
                int idx = tid + i * 256;
                int row = idx >> 2;
                int c4  = idx & 3;
                ra[i] = *(const float4*)(S + (size_t)(mbase + row) * ld + kk + c4 * 4);
            }
            rb = *(const float4*)(W + (size_t)(nbase + brow) * ldw + kg + bc4 * 4);
        }

        // ---- compute previous chunk from smem ----
        if (ch > 0) {
            int bf = (ch - 1) & 1;
            #pragma unroll
            for (int ks = 0; ks < 2; ks++) {
                int kk = ks * 8;
                unsigned ah[4][4], al[4][4], bh[2][2], bl[2][2];
                #pragma unroll
                for (int mt = 0; mt < 4; mt++) {
                    int r0 = wm * 64 + mt * 16 + gp;
                    split2(As[bf][r0    ][kk + tq],     ah[mt][0], al[mt][0]);
                    split2(As[bf][r0 + 8][kk + tq],     ah[mt][1], al[mt][1]);
                    split2(As[bf][r0    ][kk + tq + 4], ah[mt][2], al[mt][2]);
                    split2(As[bf][r0 + 8][kk + tq + 4], ah[mt][3], al[mt][3]);
                }
                #pragma unroll
                for (int nt = 0; nt < 2; nt++) {
                    int n0 = wn * 16 + nt * 8 + gp;
                    split2(Bs[bf][n0][kk + tq],     bh[nt][0], bl[nt][0]);
                    split2(Bs[bf][n0][kk + tq + 4], bh[nt][1], bl[nt][1]);
                }
                #pragma unroll
                for (int mt = 0; mt < 4; mt++)
                    #pragma unroll
                    for (int nt = 0; nt < 2; nt++) {
                        MMA(acc[mt][nt], ah[mt][0], ah[mt][1], ah[mt][2], ah[mt][3],
                            bl[nt][0], bl[nt][1]);
                        MMA(acc[mt][nt], al[mt][0], al[mt][1], al[mt][2], al[mt][3],
                            bh[nt][0], bh[nt][1]);
                        MMA(acc[mt][nt], ah[mt][0], ah[mt][1], ah[mt][2], ah[mt][3],
                            bh[nt][0], bh[nt][1]);
                    }
            }
        }

        // ---- store staged chunk to smem (raw fp32, float4) ----
        if (ch < NCH) {
            int bf = ch & 1;
            #pragma unroll
            for (int i = 0; i < 2; i++) {
                int idx = tid + i * 256;
                int row = idx >> 2;
                int c4  = idx & 3;
                *(float4*)&As[bf][row][c4 * 4] = ra[i];
            }
            *(float4*)&Bs[bf][brow][bc4 * 4] = rb;
            __syncthreads();
        }
    }

    // ---- epilogue: bias (+relu), store ----
    #pragma unroll
    for (int mt = 0; mt < 4; mt++) {
        int r0 = mbase + wm * 64 + mt * 16 + gp;
        #pragma unroll
        for (int nt = 0; nt < 2; nt++) {
            int c0 = nbase + wn * 16 + nt * 8 + tq * 2;
            float bv0 = bias[c0];
            float bv1 = bias[c0 + 1];
            float v;
            v = acc[mt][nt][0] + bv0; if (relu) v = fmaxf(v, 0.f);
            C[(size_t)r0 * ldc + c0] = v;
            v = acc[mt][nt][1] + bv1; if (relu) v = fmaxf(v, 0.f);
            C[(size_t)r0 * ldc + c0 + 1] = v;
            v = acc[mt][nt][2] + bv0; if (relu) v = fmaxf(v, 0.f);
            C[(size_t)(r0 + 8) * ldc + c0] = v;
            v = acc[mt][nt][3] + bv1; if (relu) v = fmaxf(v, 0.f);
            C[(size_t)(r0 + 8) * ldc + c0 + 1] = v;
        }
    }
}

// ---------------------------------------------------------------------------
// Mean over N of the arg half of h1:  hb[bh][c] = mean_n h1[n*BH+bh][256+c]
// ---------------------------------------------------------------------------
__global__ void meanpool_kernel(const float* __restrict__ h1, float* __restrict__ hb)
{
    int i = blockIdx.x * blockDim.x + threadIdx.x;   // 0 .. 32768*64-1 (float4s)
    int bh = i >> 6;
    int c4 = i & 63;
    float4 s = make_float4(0.f, 0.f, 0.f, 0.f);
    #pragma unroll
    for (int n = 0; n < 4; n++) {
        const float* p = h1 + (size_t)(n * BH + bh) * 512 + 256 + c4 * 4;
        float4 v = *(const float4*)p;
        s.x += v.x; s.y += v.y; s.z += v.z; s.w += v.w;
    }
    float4 o = make_float4(s.x * 0.25f, s.y * 0.25f, s.z * 0.25f, s.w * 0.25f);
    *(float4*)(hb + (size_t)bh * 256 + c4 * 4) = o;
}

// ---------------------------------------------------------------------------
// Epilogue: per (bh, d): softmax over N=4 of s, circular mean via atan
// correction; gate = sigmoid(t); arg_out = min_n(arg) * gate.
// ---------------------------------------------------------------------------
__global__ void epilogue_kernel(const float* __restrict__ axisE,
                                const float* __restrict__ argE,
                                float* __restrict__ out)
{
    int idx = blockIdx.x * blockDim.x + threadIdx.x;   // 0 .. BHD-1
    int bh = idx >> 8;
    int d  = idx & 255;

    float s[4], axv[4], agv[4];
    #pragma unroll
    for (int n = 0; n < 4; n++) {
        size_t r = (size_t)n * BH + bh;
        s[n]   = g_s[r * 256 + d];
        axv[n] = axisE[r * 256 + d];
        agv[n] = argE [r * 256 + d];
    }
    float t = g_t[(size_t)bh * 256 + d];

    float m = fmaxf(fmaxf(s[0], s[1]), fmaxf(s[2], s[3]));
    float e[4], se = 0.f;
    #pragma unroll
    for (int n = 0; n < 4; n++) { e[n] = expf(s[n] - m); se += e[n]; }
    float inv = 1.f / se;

    float x = 0.f, y = 0.f;
    #pragma unroll
    for (int n = 0; n < 4; n++) {
        float sn, cn;
        sincosf(axv[n], &sn, &cn);
        float w = e[n] * inv;
        x += w * cn;
        y += w * sn;
    }
    if (fabsf(x) < 0.001f) x = 0.001f;   // jnp.where(|x|<1e-3, +1e-3, x)
    float ao = atanf(y / x);
    if (x < 0.f) ao += (y < 0.f) ? -3.14159265358979f : 3.14159265358979f;

    float gate = 1.f / (1.f + expf(-t));
    float mn = fminf(fminf(agv[0], agv[1]), fminf(agv[2], agv[3]));

    out[idx]       = ao;
    out[BHD + idx] = mn * gate;
}

// ---------------------------------------------------------------------------
extern "C" void kernel_launch(void* const* d_in, const int* in_sizes, int n_in,
                              void* d_out, int out_size)
{
    const float* axisE = (const float*)d_in[0];
    const float* argE  = (const float*)d_in[1];
    const float* Wax1  = (const float*)d_in[2];
    const float* bax1  = (const float*)d_in[3];
    const float* Warg1 = (const float*)d_in[4];
    const float* barg1 = (const float*)d_in[5];
    const float* Wax2  = (const float*)d_in[6];
    const float* bax2  = (const float*)d_in[7];
    const float* Warg2 = (const float*)d_in[8];
    const float* barg2 = (const float*)d_in[9];

    float *h1, *sS, *hb, *tT, *w1c, *b1c;
    cudaGetSymbolAddress((void**)&h1,  g_h1);
    cudaGetSymbolAddress((void**)&sS,  g_s);
    cudaGetSymbolAddress((void**)&hb,  g_hb);
    cudaGetSymbolAddress((void**)&tT,  g_t);
    cudaGetSymbolAddress((void**)&w1c, g_w1c);
    cudaGetSymbolAddress((void**)&b1c, g_b1c);

    // Fold layer-1 weights
    prep_kernel<<<1024, 256>>>(Wax1, bax1, Warg1, barg1);

    // GEMM1: h1 = relu([axis,arg] @ W1c^T + b1c), [131072 x 512]
    gemm_tf32<<<dim3(512 / TN, R_TOTAL / TM), NTH>>>(
        axisE, 256, argE, 256, 256, 512, w1c, 512, b1c, h1, 512, 1);

    // GEMM2a: s = h1[:,0:256] @ W_axis2^T + b_axis2   [131072 x 256]
    gemm_tf32<<<dim3(256 / TN, R_TOTAL / TM), NTH>>>(
        h1, 512, h1, 512, 256, 256, Wax2, 256, bax2, sS, 256, 0);

    // Mean over N of arg-branch h1 -> hb [32768 x 256]
    meanpool_kernel<<<BH * 64 / 256, 256>>>(h1, hb);

    // GEMM2b: t = hb @ W_arg2^T + b_arg2   [32768 x 256]
    gemm_tf32<<<dim3(256 / TN, BH / TM), NTH>>>(
        hb, 256, hb, 256, 256, 256, Warg2, 256, barg2, tT, 256, 0);

    // Fused softmax / circular mean / gate epilogue
    epilogue_kernel<<<BHD / 256, 256>>>(axisE, argE, (float*)d_out);
}

// round 8
// speedup vs baseline: 1.8239x; 1.1761x over previous
#include <cuda_runtime.h>
#include <cstdint>

// Problem constants
#define R_TOTAL 131072      // N*B*H rows
#define BH      32768       // B*H
#define BHD     8388608     // B*DIM
#define TM 128
#define TN 128
#define KC 16
#define KS 20               // padded smem row stride (words)
#define NTH 256

// Scratch (device globals — no allocation allowed in kernel_launch)
__device__ float g_h1[131072 * 512];   // relu(layer1): cols 0-255 axis, 256-511 arg
__device__ float g_s [131072 * 256];   // axis logits
__device__ float g_hb[32768 * 256];    // mean over N of arg-branch h1
__device__ float g_t [32768 * 256];    // gate pre-activation
__device__ float g_w1c[512 * 512];     // folded layer-1 weights
__device__ float g_b1c[512];

// ---------------------------------------------------------------------------
// Prep: fold concat([axis-arg/2, axis+arg/2]) @ W1^T into direct weights on
// [axis, arg]:  coeff(axis) = Wlo + Whi ; coeff(arg) = (Whi - Wlo)/2
// ---------------------------------------------------------------------------
__global__ void prep_kernel(const float* __restrict__ Wax1, const float* __restrict__ bax1,
                            const float* __restrict__ Warg1, const float* __restrict__ barg1)
{
    int idx = blockIdx.x * blockDim.x + threadIdx.x;   // 0 .. 262143
    int o = idx >> 9;
    int i = idx & 511;
    const float* Ws = (o < 256) ? Wax1 : Warg1;
    int ro = o & 255;
    float w;
    if (i < 256) {
        w = Ws[ro * 512 + i] + Ws[ro * 512 + 256 + i];
    } else {
        int ii = i - 256;
        w = 0.5f * (Ws[ro * 512 + 256 + ii] - Ws[ro * 512 + ii]);
    }
    g_w1c[o * 512 + i] = w;
    if (i == 0)
        g_b1c[o] = (o < 256) ? bax1[o] : barg1[o - 256];
}

// ---------------------------------------------------------------------------
// 3xTF32 GEMM, register-split, CTA tile 128x128:
// smem holds raw fp32; fragments split in regs: hi = cvt.rna.tf32(v),
// lo = v - hi (fed unrounded; mma truncates operand mantissa in HW).
// acc += hi*lo + lo*hi + hi*hi.
// 8 warps (2x4), warp tile 64x32, mma.m16n8k8.tf32.
// grid: (x = N blocks, y = M blocks) so same-row CTAs run together (L2 reuse).
// ---------------------------------------------------------------------------
__device__ __forceinline__ unsigned f2tf(float f)
{
    unsigned u;
    asm("cvt.rna.tf32.f32 %0, %1;" : "=r"(u) : "f"(f));
    return u;
}

__device__ __forceinline__ void split2(float v, unsigned& h, unsigned& l)
{
    h = f2tf(v);
    l = __float_as_uint(v - __uint_as_float(h));
}

#define MMA(d, a0, a1, a2, a3, b0, b1)                                        \
    asm volatile(                                                             \
        "mma.sync.aligned.m16n8k8.row.col.f32.tf32.tf32.f32 "                 \
        "{%0,%1,%2,%3}, {%4,%5,%6,%7}, {%8,%9}, {%0,%1,%2,%3};"               \
        : "+f"(d[0]), "+f"(d[1]), "+f"(d[2]), "+f"(d[3])                      \
        : "r"(a0), "r"(a1), "r"(a2), "r"(a3), "r"(b0), "r"(b1))

__global__ __launch_bounds__(NTH)
void gemm_tf32(const float* __restrict__ src0, int lda0,
               const float* __restrict__ src1, int lda1, int K0, int K,
               const float* __restrict__ W, int ldw,
               const float* __restrict__ bias,
               float* __restrict__ C, int ldc, int relu)
{
    __shared__ float As[2][TM][KS];
    __shared__ float Bs[2][TN][KS];

    const int tid  = threadIdx.x;
    const int lane = tid & 31;
    const int wid  = tid >> 5;
    const int gp   = lane >> 2;      // 0..7
    const int tq   = lane & 3;       // 0..3
    const int wm   = wid >> 2;       // 0..1  (64-row half)
    const int wn   = wid & 3;        // 0..3  (32-col slice)
    const int mbase = blockIdx.y * TM;
    const int nbase = blockIdx.x * TN;

    float acc[4][4][4];
    #pragma unroll
    for (int a = 0; a < 4; a++)
        #pragma unroll
        for (int b = 0; b < 4; b++)
            #pragma unroll
            for (int c = 0; c < 4; c++) acc[a][b][c] = 0.f;

    const int NCH = K / KC;
    float4 ra[2], rb[2];

    for (int ch = 0; ch < NCH + 1; ++ch) {
        // ---- stage next chunk global -> regs ----
        if (ch < NCH) {
            int kg = ch * KC;
            const float* S;
            int ld, kk;
            if (kg < K0) { S = src0; ld = lda0; kk = kg; }
            else         { S = src1; ld = lda1; kk = kg - K0; }
            #pragma unroll
            for (int i = 0; i < 2; i++) {
                int idx = tid + i * 256;
                int row = idx >> 2;
                int c4  = idx & 3;
                ra[i] = *(const float4*)(S + (size_t)(mbase + row) * ld + kk + c4 * 4);
                rb[i] = *(const float4*)(W + (size_t)(nbase + row) * ldw + kg + c4 * 4);
            }
        }

        // ---- compute previous chunk from smem ----
        if (ch > 0) {
            int bf = (ch - 1) & 1;
            #pragma unroll
            for (int ks = 0; ks < 2; ks++) {
                int kk = ks * 8;
                unsigned ah[4][4], al[4][4], bh[4][2], bl[4][2];
                #pragma unroll
                for (int mt = 0; mt < 4; mt++) {
                    int r0 = wm * 64 + mt * 16 + gp;
                    split2(As[bf][r0    ][kk + tq],     ah[mt][0], al[mt][0]);
                    split2(As[bf][r0 + 8][kk + tq],     ah[mt][1], al[mt][1]);
                    split2(As[bf][r0    ][kk + tq + 4], ah[mt][2], al[mt][2]);
                    split2(As[bf][r0 + 8][kk + tq + 4], ah[mt][3], al[mt][3]);
                }
                #pragma unroll
                for (int nt = 0; nt < 4; nt++) {
                    int n0 = wn * 32 + nt * 8 + gp;
                    split2(Bs[bf][n0][kk + tq],     bh[nt][0], bl[nt][0]);
                    split2(Bs[bf][n0][kk + tq + 4], bh[nt][1], bl[nt][1]);
                }
                #pragma unroll
                for (int mt = 0; mt < 4; mt++)
                    #pragma unroll
                    for (int nt = 0; nt < 4; nt++) {
                        MMA(acc[mt][nt], ah[mt][0], ah[mt][1], ah[mt][2], ah[mt][3],
                            bl[nt][0], bl[nt][1]);
                        MMA(acc[mt][nt], al[mt][0], al[mt][1], al[mt][2], al[mt][3],
                            bh[nt][0], bh[nt][1]);
                        MMA(acc[mt][nt], ah[mt][0], ah[mt][1], ah[mt][2], ah[mt][3],
                            bh[nt][0], bh[nt][1]);
                    }
            }
        }

        // ---- store staged chunk to smem (raw fp32, float4) ----
        if (ch < NCH) {
            int bf = ch & 1;
            #pragma unroll
            for (int i = 0; i < 2; i++) {
                int idx = tid + i * 256;
                int row = idx >> 2;
                int c4  = idx & 3;
                *(float4*)&As[bf][row][c4 * 4] = ra[i];
                *(float4*)&Bs[bf][row][c4 * 4] = rb[i];
            }
            __syncthreads();
        }
    }

    // ---- epilogue: bias (+relu), store ----
    #pragma unroll
    for (int mt = 0; mt < 4; mt++) {
        int r0 = mbase + wm * 64 + mt * 16 + gp;
        #pragma unroll
        for (int nt = 0; nt < 4; nt++) {
            int c0 = nbase + wn * 32 + nt * 8 + tq * 2;
            float bv0 = bias[c0];
            float bv1 = bias[c0 + 1];
            float v;
            v = acc[mt][nt][0] + bv0; if (relu) v = fmaxf(v, 0.f);
            C[(size_t)r0 * ldc + c0] = v;
            v = acc[mt][nt][1] + bv1; if (relu) v = fmaxf(v, 0.f);
            C[(size_t)r0 * ldc + c0 + 1] = v;
            v = acc[mt][nt][2] + bv0; if (relu) v = fmaxf(v, 0.f);
            C[(size_t)(r0 + 8) * ldc + c0] = v;
            v = acc[mt][nt][3] + bv1; if (relu) v = fmaxf(v, 0.f);
            C[(size_t)(r0 + 8) * ldc + c0 + 1] = v;
        }
    }
}

// ---------------------------------------------------------------------------
// Mean over N of the arg half of h1:  hb[bh][c] = mean_n h1[n*BH+bh][256+c]
// ---------------------------------------------------------------------------
__global__ void meanpool_kernel(const float* __restrict__ h1, float* __restrict__ hb)
{
    int i = blockIdx.x * blockDim.x + threadIdx.x;   // 0 .. 32768*64-1 (float4s)
    int bh = i >> 6;
    int c4 = i & 63;
    float4 s = make_float4(0.f, 0.f, 0.f, 0.f);
    #pragma unroll
    for (int n = 0; n < 4; n++) {
        const float* p = h1 + (size_t)(n * BH + bh) * 512 + 256 + c4 * 4;
        float4 v = *(const float4*)p;
        s.x += v.x; s.y += v.y; s.z += v.z; s.w += v.w;
    }
    float4 o = make_float4(s.x * 0.25f, s.y * 0.25f, s.z * 0.25f, s.w * 0.25f);
    *(float4*)(hb + (size_t)bh * 256 + c4 * 4) = o;
}

// ---------------------------------------------------------------------------
// Epilogue: per (bh, d): softmax over N=4 of s, circular mean via atan
// correction; gate = sigmoid(t); arg_out = min_n(arg) * gate.
// ---------------------------------------------------------------------------
__global__ void epilogue_kernel(const float* __restrict__ axisE,
                                const float* __restrict__ argE,
                                float* __restrict__ out)
{
    int idx = blockIdx.x * blockDim.x + threadIdx.x;   // 0 .. BHD-1
    int bh = idx >> 8;
    int d  = idx & 255;

    float s[4], axv[4], agv[4];
    #pragma unroll
    for (int n = 0; n < 4; n++) {
        size_t r = (size_t)n * BH + bh;
        s[n]   = g_s[r * 256 + d];
        axv[n] = axisE[r * 256 + d];
        agv[n] = argE [r * 256 + d];
    }
    float t = g_t[(size_t)bh * 256 + d];

    float m = fmaxf(fmaxf(s[0], s[1]), fmaxf(s[2], s[3]));
    float e[4], se = 0.f;
    #pragma unroll
    for (int n = 0; n < 4; n++) { e[n] = expf(s[n] - m); se += e[n]; }
    float inv = 1.f / se;

    float x = 0.f, y = 0.f;
    #pragma unroll
    for (int n = 0; n < 4; n++) {
        float sn, cn;
        sincosf(axv[n], &sn, &cn);
        float w = e[n] * inv;
        x += w * cn;
        y += w * sn;
    }
    if (fabsf(x) < 0.001f) x = 0.001f;   // jnp.where(|x|<1e-3, +1e-3, x)
    float ao = atanf(y / x);
    if (x < 0.f) ao += (y < 0.f) ? -3.14159265358979f : 3.14159265358979f;

    float gate = 1.f / (1.f + expf(-t));
    float mn = fminf(fminf(agv[0], agv[1]), fminf(agv[2], agv[3]));

    out[idx]       = ao;
    out[BHD + idx] = mn * gate;
}

// ---------------------------------------------------------------------------
extern "C" void kernel_launch(void* const* d_in, const int* in_sizes, int n_in,
                              void* d_out, int out_size)
{
    const float* axisE = (const float*)d_in[0];
    const float* argE  = (const float*)d_in[1];
    const float* Wax1  = (const float*)d_in[2];
    const float* bax1  = (const float*)d_in[3];
    const float* Warg1 = (const float*)d_in[4];
    const float* barg1 = (const float*)d_in[5];
    const float* Wax2  = (const float*)d_in[6];
    const float* bax2  = (const float*)d_in[7];
    const float* Warg2 = (const float*)d_in[8];
    const float* barg2 = (const float*)d_in[9];

    float *h1, *sS, *hb, *tT, *w1c, *b1c;
    cudaGetSymbolAddress((void**)&h1,  g_h1);
    cudaGetSymbolAddress((void**)&sS,  g_s);
    cudaGetSymbolAddress((void**)&hb,  g_hb);
    cudaGetSymbolAddress((void**)&tT,  g_t);
    cudaGetSymbolAddress((void**)&w1c, g_w1c);
    cudaGetSymbolAddress((void**)&b1c, g_b1c);

    // Fold layer-1 weights
    prep_kernel<<<1024, 256>>>(Wax1, bax1, Warg1, barg1);

    // GEMM1: h1 = relu([axis,arg] @ W1c^T + b1c), [131072 x 512]
    gemm_tf32<<<dim3(512 / TN, R_TOTAL / TM), NTH>>>(
        axisE, 256, argE, 256, 256, 512, w1c, 512, b1c, h1, 512, 1);

    // GEMM2a: s = h1[:,0:256] @ W_axis2^T + b_axis2   [131072 x 256]
    gemm_tf32<<<dim3(256 / TN, R_TOTAL / TM), NTH>>>(
        h1, 512, h1, 512, 256, 256, Wax2, 256, bax2, sS, 256, 0);

    // Mean over N of arg-branch h1 -> hb [32768 x 256]
    meanpool_kernel<<<BH * 64 / 256, 256>>>(h1, hb);

    // GEMM2b: t = hb @ W_arg2^T + b_arg2   [32768 x 256]
    gemm_tf32<<<dim3(256 / TN, BH / TM), NTH>>>(
        hb, 256, hb, 256, 256, 256, Warg2, 256, barg2, tT, 256, 0);

    // Fused softmax / circular mean / gate epilogue
    epilogue_kernel<<<BHD / 256, 256>>>(axisE, argE, (float*)d_out);
}